// round 14
// baseline (speedup 1.0000x reference)
#include <cuda_runtime.h>
#include <cstdint>

#define BS  16
#define NA  33600
#define NG  64
#define NC  80
#define NT1 256
#define NCHUNK 132                      // ceil(33600/256); last chunk has 64 anchors
#define NCOMP (BS * NCHUNK)             // 2112 compute blocks
#define NPOLL BS                        // 16 poller blocks (one per batch)
#define NBLK  (NCOMP + NPOLL)

// ---------------- scratch (device globals; no allocation) ----------------
__device__ int      g_posAnyBlk[BS * NCHUNK];
__device__ unsigned g_done;             // compute blocks completed (self-reset)
__device__ unsigned g_fin;              // pollers finished (self-reset)

__device__ __forceinline__ bool fgt(float n1, float d1, float n2, float d2) {
    return __fmul_rn(n1, d2) > __fmul_rn(n2, d1);
}

__device__ __forceinline__ void ins3(float n, float d,
    float& t0n, float& t0d, float& t1n, float& t1d, float& t2n, float& t2d) {
    if (fgt(n, d, t2n, t2d)) {
        if (fgt(n, d, t1n, t1d)) {
            t2n = t1n; t2d = t1d;
            if (fgt(n, d, t0n, t0d)) { t1n = t0n; t1d = t0d; t0n = n; t0d = d; }
            else                     { t1n = n;   t1d = d; }
        } else { t2n = n; t2d = d; }
    }
}

// ========== single kernel: compute blocks + 16 poller/fallback blocks =====
__global__ __launch_bounds__(NT1, 8)    // cap regs at 32: protect hot path
void k1f(const float4* __restrict__ pd,
         const float4* __restrict__ gt,
         const int*    __restrict__ mg,
         const int*    __restrict__ glRaw,
         float*  __restrict__ outLab,
         float4* __restrict__ outBox,
         float*  __restrict__ outFg,
         float*  __restrict__ outTgi,
         float*  __restrict__ outScores) {
    __shared__ float4 sboxc[NG];     // compacted valid boxes
    __shared__ float  sareac[NG];
    __shared__ int    sgidxc[NG];
    __shared__ float4 sbox0[NG];     // original boxes
    __shared__ int    slab[NG];
    __shared__ int    svalid[NG];
    __shared__ int    scnt[2];
    __shared__ int    snv, sl64;
    __shared__ __align__(16) float4 szero4[64 * NC / 4];  // 20 KB zero buffer

    const int cb  = blockIdx.x;
    const int tid = threadIdx.x;

    // ======================= poller / fallback role =======================
    if (cb >= NCOMP) {
        const int b = cb - NCOMP;
        // spin until every compute block has released its writes
        if (tid == 0) {
            unsigned vv;
            do {
                asm volatile("ld.acquire.gpu.global.u32 %0, [%1];"
                             : "=r"(vv) : "l"(&g_done));
            } while (vv < (unsigned)NCOMP);
        }
        __syncthreads();   // acquire propagates to whole block via barrier

        int f  = (tid < NCHUNK) ? g_posAnyBlk[b * NCHUNK + tid] : 0;
        int anyP = __syncthreads_or(f);
        int hv   = __syncthreads_or((tid < NG) ? (mg[b * NG + tid] != 0) : 0);

        if (!anyP && hv) {
            // ---------- fallback (statistically never executes) ----------
            if (tid == 0)
                sl64 = ((glRaw[1] | glRaw[3] | glRaw[5] | glRaw[7] |
                         glRaw[9] | glRaw[11]) == 0);
            __syncthreads();
            if (tid < NG) {
                int v = mg[b * NG + tid];
                float4 q = gt[b * NG + tid];
                if (v == 0) q = make_float4(0.f, 0.f, 0.f, 0.f);
                sbox0[tid]  = q;
                sareac[tid] = __fmul_rn(__fsub_rn(q.z, q.x), __fsub_rn(q.w, q.y));
                svalid[tid] = v;
                slab[tid]   = sl64 ? (int)((const long long*)glRaw)[b * NG + tid]
                                   : glRaw[b * NG + tid];
            }
            __syncthreads();

            // reduction scratch carved from the zero buffer
            float* s0n = (float*)szero4;
            float* s0d = s0n + NT1;
            float* s1n = s0d + NT1;
            float* s1d = s1n + NT1;
            float* s2n = s1d + NT1;
            float* s2d = s2n + NT1;

            // phase 1: batch-wide top-3 over valid GT fractions
            float t0n = -1.f, t0d = 1.f, t1n = -1.f, t1d = 1.f,
                  t2n = -1.f, t2d = 1.f;
            for (int a = tid; a < NA; a += NT1) {
                float4 p = pd[b * NA + a];
                float parea = __fmul_rn(__fsub_rn(p.z, p.x), __fsub_rn(p.w, p.y));
                for (int g = 0; g < NG; g++) {
                    if (!svalid[g]) continue;
                    float4 q = sbox0[g];
                    float iw = fmaxf(__fsub_rn(fminf(q.z, p.z), fmaxf(q.x, p.x)), 0.f);
                    float ih = fmaxf(__fsub_rn(fminf(q.w, p.w), fmaxf(q.y, p.y)), 0.f);
                    float num = __fmul_rn(iw, ih);
                    float den = __fadd_rn(__fsub_rn(__fadd_rn(sareac[g], parea), num), 1e-9f);
                    ins3(num, den, t0n, t0d, t1n, t1d, t2n, t2d);
                }
            }
            s0n[tid] = t0n; s0d[tid] = t0d;
            s1n[tid] = t1n; s1d[tid] = t1d;
            s2n[tid] = t2n; s2d[tid] = t2d;
            __syncthreads();
            for (int off = NT1 / 2; off > 0; off >>= 1) {
                if (tid < off) {
                    float m0n = s0n[tid], m0d = s0d[tid], m1n = s1n[tid],
                          m1d = s1d[tid], m2n = s2n[tid], m2d = s2d[tid];
                    int j = tid + off;
                    ins3(s0n[j], s0d[j], m0n, m0d, m1n, m1d, m2n, m2d);
                    ins3(s1n[j], s1d[j], m0n, m0d, m1n, m1d, m2n, m2d);
                    ins3(s2n[j], s2d[j], m0n, m0d, m1n, m1d, m2n, m2d);
                    s0n[tid] = m0n; s0d[tid] = m0d;
                    s1n[tid] = m1n; s1d[tid] = m1d;
                    s2n[tid] = m2n; s2d[tid] = m2d;
                }
                __syncthreads();
            }
            const float minIou = __fdiv_rn(s2n[0], s2d[0]);
            __syncthreads();

            // phase 2: recompute argmax, rewrite all outputs
            for (int a = tid; a < NA; a += NT1) {
                float4 p = pd[b * NA + a];
                float parea = __fmul_rn(__fsub_rn(p.z, p.x), __fsub_rn(p.w, p.y));
                float b0n = 0.f, b0d = 1.f, b1n = 0.f, b1d = 1.f;
                int   i0 = 0, i1 = 0;
                for (int g = 0; g < NG; g++) {
                    float4 q = sbox0[g];
                    float iw = fmaxf(__fsub_rn(fminf(q.z, p.z), fmaxf(q.x, p.x)), 0.f);
                    float ih = fmaxf(__fsub_rn(fminf(q.w, p.w), fmaxf(q.y, p.y)), 0.f);
                    float num = __fmul_rn(iw, ih);
                    float den = __fadd_rn(__fsub_rn(__fadd_rn(sareac[g], parea), num), 1e-9f);
                    if (__fmul_rn(num, b1d) > __fmul_rn(b1n, den)) {
                        if (__fmul_rn(num, b0d) > __fmul_rn(b0n, den)) {
                            b1n = b0n; b1d = b0d; i1 = i0;
                            b0n = num; b0d = den; i0 = g;
                        } else {
                            b1n = num; b1d = den; i1 = g;
                        }
                    }
                }
                float r0 = __fdiv_rn(b0n, b0d);
                float r1 = __fdiv_rn(b1n, b1d);
                int tgi = i0;
                if (r1 == r0 && i1 < i0) tgi = i1;

                const int idx = b * NA + a;
                bool fg   = r0 >= minIou;
                bool va   = svalid[tgi] != 0;
                bool mask = fg && va;
                int  lab  = slab[tgi];

                outLab[idx] = mask ? (float)lab : (float)NC;
                float4 bx = gt[b * NG + tgi];
                outBox[idx] = mask ? bx : make_float4(0.f, 0.f, 0.f, 0.f);
                outFg[idx]  = fg ? 1.f : 0.f;
                outTgi[idx] = (float)tgi;
                if (mask) outScores[(size_t)idx * NC + lab] = 1.f;  // row all-zero
            }
        }

        // retire: last poller resets both counters for the next graph replay
        __syncthreads();
        if (tid == 0) {
            unsigned n = atomicAdd(&g_fin, 1u);
            if (n == NPOLL - 1) { g_done = 0; g_fin = 0; }
        }
        return;
    }

    // ========================== compute role ==============================
    const int b     = cb / NCHUNK;
    const int chunk = cb % NCHUNK;

    int v = 0; unsigned bm = 0; float4 q;
    if (tid < NG) {
        v = mg[b * NG + tid];
        q = gt[b * NG + tid];
        bm = __ballot_sync(0xffffffffu, v != 0);
        if ((tid & 31) == 0) scnt[tid >> 5] = __popc(bm);
        sbox0[tid]  = q;
        svalid[tid] = v;
    }
    if (tid == 0)
        sl64 = ((glRaw[1] | glRaw[3] | glRaw[5] | glRaw[7] | glRaw[9] | glRaw[11]) == 0);

    // zero the TMA source buffer once (5 float4 per thread)
    #pragma unroll
    for (int i = 0; i < 64 * NC / 4 / NT1; i++)
        szero4[tid + i * NT1] = make_float4(0.f, 0.f, 0.f, 0.f);

    __syncthreads();   // scnt/szero4 visible before compaction reads scnt[0]

    if (tid < NG) {
        slab[tid] = sl64 ? (int)((const long long*)glRaw)[b * NG + tid]
                         : glRaw[b * NG + tid];
        if (v) {
            int pos = __popc(bm & ((1u << (tid & 31)) - 1)) + ((tid >= 32) ? scnt[0] : 0);
            sboxc[pos]  = q;
            sareac[pos] = __fmul_rn(__fsub_rn(q.z, q.x), __fsub_rn(q.w, q.y));
            sgidxc[pos] = tid;
        }
        if (tid == 0) snv = scnt[0] + scnt[1];
    }
    __syncthreads();

    // ---- issue ALL zero-copies up front: TMA overlaps the compute below ---
    const int aBase = chunk * NT1;
    const int remA  = min(NT1, NA - aBase);
    const int nCp   = (remA + 63) / 64;             // 4 (1 for last chunk)
    if (tid == 0) {
        asm volatile("fence.proxy.async.shared::cta;" ::: "memory");
        uint32_t saddr = (uint32_t)__cvta_generic_to_shared(szero4);
        float* gbase = outScores + ((size_t)b * NA + (size_t)aBase) * NC;
        for (int c = 0; c < nCp; c++) {
            int nA = min(64, remA - c * 64);
            asm volatile(
                "cp.async.bulk.global.shared::cta.bulk_group [%0], [%1], %2;"
                :: "l"(gbase + (size_t)c * 64 * NC), "r"(saddr),
                   "r"(nA * NC * 4) : "memory");
        }
        asm volatile("cp.async.bulk.commit_group;" ::: "memory");
    }

    // --------------------------- compute ----------------------------------
    const int a = aBase + tid;
    bool posAny = false;
    int  packed = 0;

    if (a < NA) {
        float4 p = pd[b * NA + a];
        float parea = __fmul_rn(__fsub_rn(p.z, p.x), __fsub_rn(p.w, p.y));
        float b0n = 0.f, b0d = 1.f, b1n = 0.f, b1d = 1.f;
        int   i0 = 0, i1 = 0;
        const int nv = snv;
        #pragma unroll 4
        for (int j = 0; j < nv; j++) {
            float4 qq = sboxc[j];
            float iw = fmaxf(__fsub_rn(fminf(qq.z, p.z), fmaxf(qq.x, p.x)), 0.f);
            float ih = fmaxf(__fsub_rn(fminf(qq.w, p.w), fmaxf(qq.y, p.y)), 0.f);
            float num = __fmul_rn(iw, ih);
            float den = __fadd_rn(__fsub_rn(__fadd_rn(sareac[j], parea), num), 1e-9f);
            if (__fmul_rn(num, b1d) > __fmul_rn(b1n, den)) {
                int g = sgidxc[j];
                if (__fmul_rn(num, b0d) > __fmul_rn(b0n, den)) {
                    b1n = b0n; b1d = b0d; i1 = i0;
                    b0n = num; b0d = den; i0 = g;
                } else {
                    b1n = num; b1d = den; i1 = g;
                }
            }
        }
        float r0 = __fdiv_rn(b0n, b0d);
        float r1 = __fdiv_rn(b1n, b1d);
        int bi = i0;
        if (r1 == r0 && i1 < i0) bi = i1;
        posAny = r0 > 0.3f;

        const int idx = b * NA + a;
        bool mask = posAny && (svalid[bi] != 0);
        int  lab  = slab[bi];

        __stcs(&outLab[idx], mask ? (float)lab : (float)NC);
        float4 bx = sbox0[bi];
        __stcs(&outBox[idx], mask ? bx : make_float4(0.f, 0.f, 0.f, 0.f));
        __stcs(&outFg[idx],  posAny ? 1.f : 0.f);
        __stcs(&outTgi[idx], (float)bi);
        packed = lab | (mask ? 0x100 : 0);
    }
    int anyBlk = __syncthreads_or(posAny ? 1 : 0);
    if (tid == 0) g_posAnyBlk[b * NCHUNK + chunk] = anyBlk;

    // ---- wait for zero-copies, then scatter the sparse ones ---------------
    if (tid == 0)
        asm volatile("cp.async.bulk.wait_group 0;" ::: "memory");
    __syncthreads();                     // TMA zeros complete & visible
    if (packed & 0x100) {
        const int idx = b * NA + a;
        outScores[(size_t)idx * NC + (packed & 0xFF)] = 1.f;
    }

    // ---- signal completion: release orders all block writes + flag store --
    // (bar.sync gives intra-block HB; wait_group retired the TMA writes)
    if (tid == 0)
        asm volatile("red.release.gpu.global.add.u32 [%0], %1;"
                     :: "l"(&g_done), "r"(1u) : "memory");
}

// ------------------------------ entry point -------------------------------
// inputs: 0 pd_scores, 1 pd_bboxes, 2 anc_points, 3 gt_labels, 4 gt_bboxes, 5 mask_gt
// output: float32 concat [labels | bboxes | scores | fg_mask | tgi]
extern "C" void kernel_launch(void* const* d_in, const int* in_sizes, int n_in,
                              void* d_out, int out_size) {
    const float4* pd = (const float4*)d_in[1];
    const int*    gl = (const int*)d_in[3];
    const float4* gt = (const float4*)d_in[4];
    const int*    mg = (const int*)d_in[5];

    float* out = (float*)d_out;
    const size_t E = (size_t)BS * NA;
    float*  outLab    = out;
    float4* outBox    = (float4*)(out + E);
    float*  outScores = out + E * 5;
    float*  outFg     = out + E * 85;
    float*  outTgi    = out + E * 86;

    k1f<<<NBLK, NT1>>>(pd, gt, mg, gl, outLab, outBox, outFg, outTgi, outScores);
}